// round 2
// baseline (speedup 1.0000x reference)
#include <cuda_runtime.h>
#include <cstdint>
#include <cstddef>
#include <math.h>

#define B_TOTAL 512
#define T_LEN   256
#define HID     128
#define G4      512
#define WINDOW  8
#define ENCO    128
#define R_ROWS  4
#define NCTA    128
#define NTHR    256
#define K_SM_PAIRS   48
#define K_TAIL_PAIRS 16
#define BT      (B_TOTAL * T_LEN)

typedef unsigned long long ull;

__device__ __forceinline__ ull ffma2(ull a, ull b, ull c) {
    ull d;
    asm("fma.rn.f32x2 %0, %1, %2, %3;" : "=l"(d) : "l"(a), "l"(b), "l"(c));
    return d;
}
__device__ __forceinline__ float lo32(ull v) { return __uint_as_float((unsigned)v); }
__device__ __forceinline__ float hi32(ull v) { return __uint_as_float((unsigned)(v >> 32)); }
__device__ __forceinline__ ull pack2(float a, float b) {
    return (ull)__float_as_uint(a) | ((ull)__float_as_uint(b) << 32);
}
__device__ __forceinline__ float sigf(float x) { return 1.0f / (1.0f + expf(-x)); }

struct Smem {
    ull   Wp[K_SM_PAIRS][G4];     // 196608 B : W_hh pairs, k-pair-major
    ull   h2[R_ROWS][HID/2];      //   2048 B : hidden state as packed pairs
    float g[R_ROWS][G4];          //   8192 B : gate pre-activations (also init staging)
    float wih[5][G4];             //  10240 B : W_ih transposed
    float btot[G4];               //   2048 B : b_ih + b_hh
    float tout[R_ROWS][T_LEN];    //   4096 B
    float intv[R_ROWS][T_LEN];    //   4096 B : precomputed int_all
    float xv[R_ROWS][WINDOW][5];  //    640 B
    float fc1b[HID];              //    512 B
    float fc2w[HID];              //    512 B
    float Esm[R_ROWS];            //     16 B
    float red[R_ROWS][4];         //     64 B
};

// fc1 weights as transposed pairs: g_fc1p[k2*HID + u] = pack(fc1_w[u][2k2], fc1_w[u][2k2+1])
__device__ ull g_fc1p[64 * HID];

__global__ void prep_fc1(const float* __restrict__ fc1_w) {
    int idx = blockIdx.x * blockDim.x + threadIdx.x;
    if (idx < 64 * HID) {
        int k2 = idx >> 7, u = idx & 127;
        g_fc1p[idx] = pack2(fc1_w[u * HID + 2 * k2], fc1_w[u * HID + 2 * k2 + 1]);
    }
}

__global__ __launch_bounds__(NTHR, 1)
void modnn_kernel(const float* __restrict__ X,
                  const float* __restrict__ W_ih, const float* __restrict__ W_hh,
                  const float* __restrict__ b_ih, const float* __restrict__ b_hh,
                  const float* __restrict__ fc1_b,
                  const float* __restrict__ fc2_w, const float* __restrict__ fc2_b,
                  const float* __restrict__ int1_w, const float* __restrict__ int1_b,
                  const float* __restrict__ int3_w, const float* __restrict__ int3_b,
                  const float* __restrict__ scale_w, const float* __restrict__ zone_w,
                  float* __restrict__ out)
{
    extern __shared__ char smem_raw[];
    Smem* s = reinterpret_cast<Smem*>(smem_raw);
    const int tid = threadIdx.x;
    const int b0  = blockIdx.x * R_ROWS;

    // ---- stage weights ----
    for (int idx = tid; idx < K_SM_PAIRS * G4; idx += NTHR) {
        int k2 = idx >> 9, o = idx & 511;
        const float* wr = W_hh + (size_t)o * HID + 2 * k2;
        s->Wp[k2][o] = pack2(wr[0], wr[1]);
    }
    for (int idx = tid; idx < 5 * G4; idx += NTHR) {
        int j = idx >> 9, o = idx & 511;
        s->wih[j][o] = W_ih[o * 5 + j];
    }
    for (int idx = tid; idx < G4; idx += NTHR)
        s->btot[idx] = b_ih[idx] + b_hh[idx];
    if (tid < HID) { s->fc1b[tid] = fc1_b[tid]; s->fc2w[tid] = fc2_w[tid]; }

    // stage int-module weights into g area (reused later)
    {
        float* tmp = &s->g[0][0];   // [0:384)=int1_w, [384:512)=int1_b, [512:640)=int3_w
        for (int idx = tid; idx < HID * 3; idx += NTHR) tmp[idx] = int1_w[idx];
        for (int idx = tid; idx < HID; idx += NTHR) {
            tmp[384 + idx] = int1_b[idx];
            tmp[512 + idx] = int3_w[idx];
        }
    }

    // ---- W_hh tail (k-pairs 48..63) in registers ----
    ull wt0[K_TAIL_PAIRS], wt1[K_TAIL_PAIRS];
    {
        const ull* p0 = reinterpret_cast<const ull*>(W_hh + (size_t)tid * HID + 2 * K_SM_PAIRS);
        const ull* p1 = reinterpret_cast<const ull*>(W_hh + (size_t)(tid + 256) * HID + 2 * K_SM_PAIRS);
        #pragma unroll
        for (int j = 0; j < K_TAIL_PAIRS; ++j) { wt0[j] = p0[j]; wt1[j] = p1[j]; }
    }

    const float zone = zone_w[0];
    const float fcb2 = fc2_b[0];
    const float i3b  = int3_b[0];
    const float scl  = scale_w[0];
    __syncthreads();

    // ---- precompute int_all; emit constant outputs; init tout/h/Esm ----
    {
        const float* tmp = &s->g[0][0];
        for (int it = tid; it < R_ROWS * T_LEN; it += NTHR) {
            int r = it >> 8, tt = it & 255;
            const float* Xb = X + (size_t)(b0 + r) * (T_LEN * 7) + tt * 7;
            float x0 = Xb[3], x1 = Xb[4], x2 = Xb[5];
            float acc = 0.f;
            #pragma unroll 8
            for (int u = 0; u < HID; ++u) {
                float v = fmaf(tmp[u*3], x0, fmaf(tmp[u*3+1], x1, fmaf(tmp[u*3+2], x2, tmp[384+u])));
                v = fmaxf(v, 0.f);
                acc = fmaf(v, tmp[512 + u], acc);
            }
            float val = scl * sigf(acc + i3b);
            s->intv[r][tt] = val;
            size_t base = (size_t)(b0 + r) * T_LEN + tt;
            out[(size_t)BT + base]   = Xb[6];                          // HVAC_list
            out[3*(size_t)BT + base] = (tt >= WINDOW) ? val : 0.f;     // Int_list
            if (tt < WINDOW) {
                out[base]                = Xb[0];                      // TOut[:, :w] = T0
                out[2*(size_t)BT + base] = 0.f;                        // Ext_list zeros
                s->tout[r][tt] = Xb[0];
            }
        }
        for (int idx = tid; idx < R_ROWS * (HID/2); idx += NTHR)
            s->h2[idx >> 6][idx & 63] = pack2(1.f, 1.f);
        if (tid < R_ROWS)
            s->Esm[tid] = X[(size_t)(b0 + tid) * (T_LEN * 7) + WINDOW * 7];  // T0[:, 8]
    }
    float c0 = 1.f, c1 = 1.f;
    const int rA = tid >> 7;   // phase-2 / fc1 row group: rows rA and rA+2
    const int uu = tid & 127;
    __syncthreads();

    // ================= main sequential time loop =================
    for (int i = WINDOW; i < T_LEN; ++i) {
        const bool  enc   = (i < ENCO);
        const float ratio = enc ? (float)i * (1.f / ENCO) : 0.f;

        // ---- window build: TOut[:, i] = E(old); embed inputs ----
        if (tid < R_ROWS * WINDOW) {
            int r = tid >> 3, tt = tid & 7;
            int pos = i - (WINDOW - 1) + tt;
            const float* Xb = X + (size_t)(b0 + r) * (T_LEN * 7);
            float TO;
            if (tt == WINDOW - 1) {
                TO = s->Esm[r];
                s->tout[r][i] = TO;
                out[(size_t)(b0 + r) * T_LEN + i] = TO;
            } else {
                TO = s->tout[r][pos];
            }
            float e0 = enc ? fmaf(Xb[pos * 7], ratio, TO * (1.f - ratio)) : TO;
            s->xv[r][tt][0] = e0;
            #pragma unroll
            for (int j = 1; j < 5; ++j) s->xv[r][tt][j] = Xb[pos * 7 + j];
        }
        __syncthreads();

        // ---- 8 LSTM sub-steps ----
        #pragma unroll 1
        for (int st = 0; st < WINDOW; ++st) {
            // phase 1: gates for outputs o0=tid, o1=tid+256, all 4 rows
            float init0[R_ROWS], init1[R_ROWS];
            {
                float bb0 = s->btot[tid], bb1 = s->btot[tid + 256];
                #pragma unroll
                for (int r = 0; r < R_ROWS; ++r) {
                    float v0 = bb0, v1 = bb1;
                    #pragma unroll
                    for (int j = 0; j < 5; ++j) {
                        float xj = s->xv[r][st][j];
                        v0 = fmaf(xj, s->wih[j][tid],       v0);
                        v1 = fmaf(xj, s->wih[j][tid + 256], v1);
                    }
                    init0[r] = v0; init1[r] = v1;
                }
            }
            ull a00 = 0, a01 = 0, a02 = 0, a03 = 0;
            ull a10 = 0, a11 = 0, a12 = 0, a13 = 0;
            const ull* hp0 = s->h2[0];
            const ull* hp1 = s->h2[1];
            const ull* hp2 = s->h2[2];
            const ull* hp3 = s->h2[3];
            #pragma unroll 8
            for (int k2 = 0; k2 < K_SM_PAIRS; ++k2) {
                ull w0 = s->Wp[k2][tid];
                ull w1 = s->Wp[k2][tid + 256];
                ull h0 = hp0[k2], h1 = hp1[k2], h2 = hp2[k2], h3 = hp3[k2];
                a00 = ffma2(w0, h0, a00);  a10 = ffma2(w1, h0, a10);
                a01 = ffma2(w0, h1, a01);  a11 = ffma2(w1, h1, a11);
                a02 = ffma2(w0, h2, a02);  a12 = ffma2(w1, h2, a12);
                a03 = ffma2(w0, h3, a03);  a13 = ffma2(w1, h3, a13);
            }
            #pragma unroll
            for (int j = 0; j < K_TAIL_PAIRS; ++j) {
                ull h0 = hp0[K_SM_PAIRS + j], h1 = hp1[K_SM_PAIRS + j];
                ull h2 = hp2[K_SM_PAIRS + j], h3 = hp3[K_SM_PAIRS + j];
                a00 = ffma2(wt0[j], h0, a00);  a10 = ffma2(wt1[j], h0, a10);
                a01 = ffma2(wt0[j], h1, a01);  a11 = ffma2(wt1[j], h1, a11);
                a02 = ffma2(wt0[j], h2, a02);  a12 = ffma2(wt1[j], h2, a12);
                a03 = ffma2(wt0[j], h3, a03);  a13 = ffma2(wt1[j], h3, a13);
            }
            s->g[0][tid]       = init0[0] + lo32(a00) + hi32(a00);
            s->g[1][tid]       = init0[1] + lo32(a01) + hi32(a01);
            s->g[2][tid]       = init0[2] + lo32(a02) + hi32(a02);
            s->g[3][tid]       = init0[3] + lo32(a03) + hi32(a03);
            s->g[0][tid + 256] = init1[0] + lo32(a10) + hi32(a10);
            s->g[1][tid + 256] = init1[1] + lo32(a11) + hi32(a11);
            s->g[2][tid + 256] = init1[2] + lo32(a12) + hi32(a12);
            s->g[3][tid + 256] = init1[3] + lo32(a13) + hi32(a13);
            __syncthreads();

            // phase 2: c/h update for (row rA, uu) and (row rA+2, uu)
            {
                float* hf = reinterpret_cast<float*>(&s->h2[0][0]);
                {
                    int r = rA;
                    float gi = s->g[r][uu], gf = s->g[r][uu + 128];
                    float gg = s->g[r][uu + 256], go = s->g[r][uu + 384];
                    c0 = sigf(gf) * c0 + sigf(gi) * tanhf(gg);
                    hf[r * HID + uu] = sigf(go) * tanhf(c0);
                }
                {
                    int r = rA + 2;
                    float gi = s->g[r][uu], gf = s->g[r][uu + 128];
                    float gg = s->g[r][uu + 256], go = s->g[r][uu + 384];
                    c1 = sigf(gf) * c1 + sigf(gi) * tanhf(gg);
                    hf[r * HID + uu] = sigf(go) * tanhf(c1);
                }
            }
            __syncthreads();
        }

        // ---- ext_module head: o = relu(fc1 h + b); ext = o . fc2_w + b ----
        {
            const ull* hA = s->h2[rA];
            const ull* hB = s->h2[rA + 2];
            ull A0 = 0, A1 = 0;
            #pragma unroll 8
            for (int k2 = 0; k2 < 64; ++k2) {
                ull w = __ldg(&g_fc1p[k2 * HID + uu]);
                A0 = ffma2(w, hA[k2], A0);
                A1 = ffma2(w, hB[k2], A1);
            }
            float b1 = s->fc1b[uu], w2 = s->fc2w[uu];
            float p0 = fmaxf(lo32(A0) + hi32(A0) + b1, 0.f) * w2;
            float p1 = fmaxf(lo32(A1) + hi32(A1) + b1, 0.f) * w2;
            #pragma unroll
            for (int m = 16; m > 0; m >>= 1) {
                p0 += __shfl_xor_sync(0xFFFFFFFFu, p0, m);
                p1 += __shfl_xor_sync(0xFFFFFFFFu, p1, m);
            }
            if ((tid & 31) == 0) {
                int w8 = tid >> 5;             // 0..7
                s->red[rA][w8 & 3]     = p0;   // row rA
                s->red[rA + 2][w8 & 3] = p1;   // row rA+2
            }
        }
        __syncthreads();

        // ---- scalar tail: ext, total, E update (one thread per row) ----
        if (tid < R_ROWS) {
            int r = tid;
            float dot = s->red[r][0] + s->red[r][1] + s->red[r][2] + s->red[r][3];
            float ext = dot + fcb2;
            const float* Xb = X + (size_t)(b0 + r) * (T_LEN * 7);
            float hv = Xb[i * 7 + 6];
            float it = s->intv[r][i];
            float total = ext + hv + it;
            out[2*(size_t)BT + (size_t)(b0 + r) * T_LEN + i] = ext;
            float E = s->Esm[r];
            if (enc) E = ratio * Xb[i * 7] + (1.f - ratio) * E + total * zone;
            else     E = total * zone + E;
            s->Esm[r] = E;
        }
        __syncthreads();
    }
}

extern "C" void kernel_launch(void* const* d_in, const int* in_sizes, int n_in,
                              void* d_out, int out_size) {
    const float* X       = (const float*)d_in[0];
    const float* W_ih    = (const float*)d_in[1];
    const float* W_hh    = (const float*)d_in[2];
    const float* b_ih    = (const float*)d_in[3];
    const float* b_hh    = (const float*)d_in[4];
    const float* fc1_w   = (const float*)d_in[5];
    const float* fc1_b   = (const float*)d_in[6];
    const float* fc2_w   = (const float*)d_in[7];
    const float* fc2_b   = (const float*)d_in[8];
    const float* int1_w  = (const float*)d_in[9];
    const float* int1_b  = (const float*)d_in[10];
    const float* int3_w  = (const float*)d_in[11];
    const float* int3_b  = (const float*)d_in[12];
    const float* scale_w = (const float*)d_in[13];
    const float* zone_w  = (const float*)d_in[14];
    float* out = (float*)d_out;

    prep_fc1<<<64, 128>>>(fc1_w);

    size_t smem = sizeof(Smem);
    cudaFuncSetAttribute(modnn_kernel, cudaFuncAttributeMaxDynamicSharedMemorySize, (int)smem);
    modnn_kernel<<<NCTA, NTHR, smem>>>(X, W_ih, W_hh, b_ih, b_hh,
                                       fc1_b, fc2_w, fc2_b,
                                       int1_w, int1_b, int3_w, int3_b,
                                       scale_w, zone_w, out);
}